// round 7
// baseline (speedup 1.0000x reference)
#include <cuda_runtime.h>
#include <cstdint>

#define BS 128
#define NC 1024
#define U  512
#define F  512
#define FOURU 2048
#define KTOT 1024

typedef unsigned int  uint;
typedef unsigned short ushort;

// ---------------- scratch (no allocations allowed) ----------------
__device__ float  g_h0[BS * U];
__device__ float  g_c0[BS * U];
__device__ int    g_idx[BS];
__device__ float  g_zpart[4][BS * FOURU];         // z = sum of 4 K-slices + bias
__device__ ushort g_Ah[BS * KTOT];                // A=[x|h0] hi plane, [m][k]
__device__ ushort g_Al[BS * KTOT];                // lo plane
__device__ ushort g_Bth[FOURU * KTOT];            // B=[kernel;rec] hi, TRANSPOSED [n][k]
__device__ ushort g_Btl[FOURU * KTOT];            // lo, transposed

// ---------------- helpers ----------------
__device__ __forceinline__ ushort f2bf(float a) {
    ushort u;
    asm("cvt.rn.bf16.f32 %0, %1;" : "=h"(u) : "f"(a));
    return u;
}
__device__ __forceinline__ float bf2f(ushort u) {
    float f;
    asm("cvt.f32.bf16 %0, %1;" : "=f"(f) : "h"(u));
    return f;
}
__device__ __forceinline__ void atomicMaxFloat(float* addr, float val) {
    int* ia = (int*)addr;
    int old = *ia;
    while (__int_as_float(old) < val) {
        int assumed = old;
        old = atomicCAS(ia, assumed, __float_as_int(val));
        if (old == assumed) break;
    }
}
__device__ __forceinline__ float fsig(float x) {
    float e, r;
    asm("ex2.approx.ftz.f32 %0, %1;" : "=f"(e) : "f"(-x * 1.4426950408889634f));
    asm("rcp.approx.ftz.f32 %0, %1;" : "=f"(r) : "f"(1.0f + e));
    return r;
}
__device__ __forceinline__ float ftanh_fast(float x) {
    return 2.0f * fsig(2.0f * x) - 1.0f;
}
__device__ __forceinline__ void mma16816(float* d, uint a0, uint a1, uint a2, uint a3,
                                         uint b0, uint b1) {
    asm volatile(
        "mma.sync.aligned.m16n8k16.row.col.f32.bf16.bf16.f32 "
        "{%0,%1,%2,%3}, {%4,%5,%6,%7}, {%8,%9}, {%0,%1,%2,%3};"
        : "+f"(d[0]), "+f"(d[1]), "+f"(d[2]), "+f"(d[3])
        : "r"(a0), "r"(a1), "r"(a2), "r"(a3), "r"(b0), "r"(b1));
}

// ---------------- K1: per-row argmax of logits + gather states ----------------
__global__ void k_argmax_gather(const float* __restrict__ logits,
                                const float* __restrict__ h_states,
                                const float* __restrict__ c_states) {
    const int b = blockIdx.x;
    const int t = threadIdx.x;                 // 256 threads
    const float* row = logits + b * NC;

    float best = -3.4e38f;
    int   bi   = 0x7fffffff;
#pragma unroll
    for (int j = 0; j < NC; j += 256) {
        float v = row[j + t];
        int   i = j + t;
        if (v > best || (v == best && i < bi)) { best = v; bi = i; }
    }
#pragma unroll
    for (int off = 16; off; off >>= 1) {
        float ov = __shfl_down_sync(0xffffffffu, best, off);
        int   oi = __shfl_down_sync(0xffffffffu, bi,   off);
        if (ov > best || (ov == best && oi < bi)) { best = ov; bi = oi; }
    }
    __shared__ float sv[8];
    __shared__ int   si[8];
    __shared__ int   s_idx;
    if ((t & 31) == 0) { sv[t >> 5] = best; si[t >> 5] = bi; }
    __syncthreads();
    if (t == 0) {
        best = sv[0]; bi = si[0];
#pragma unroll
        for (int w = 1; w < 8; ++w)
            if (sv[w] > best || (sv[w] == best && si[w] < bi)) { best = sv[w]; bi = si[w]; }
        s_idx = bi;
        g_idx[b] = bi;
    }
    __syncthreads();
    const int idx = s_idx;

    const float4* hs = (const float4*)(h_states + idx * U);
    const float4* cs = (const float4*)(c_states + idx * U);
    float4* hd = (float4*)(g_h0 + b * U);
    float4* cd = (float4*)(g_c0 + b * U);
    if (t < U / 4) { hd[t] = hs[t]; cd[t] = cs[t]; }
}

// ---------------- K2: copy states into output (base for scatter-max) ----------------
__global__ void k_copy_states(const float* __restrict__ h_states,
                              const float* __restrict__ c_states,
                              float* __restrict__ out_newh,
                              float* __restrict__ out_newc) {
    int i = blockIdx.x * blockDim.x + threadIdx.x;
    if (i < NC * U / 4) {
        ((float4*)out_newh)[i] = ((const float4*)h_states)[i];
        ((float4*)out_newc)[i] = ((const float4*)c_states)[i];
    }
}

// ---------------- K2b: convert A = [x | h0] into hi/lo bf16 planes ----------------
__global__ void k_convert_A(const float* __restrict__ x) {
    const int i4 = (blockIdx.x * 256 + threadIdx.x) * 4;   // 128 blocks x 256
    const int m = i4 >> 10;
    const int k = i4 & (KTOT - 1);
    float4 v;
    if (k < F) v = *(const float4*)(x + m * F + k);
    else       v = *(const float4*)(g_h0 + m * U + (k - F));

    ushort h[4], l[4];
    float* vp = (float*)&v;
#pragma unroll
    for (int j = 0; j < 4; ++j) {
        h[j] = f2bf(vp[j]);
        l[j] = f2bf(vp[j] - bf2f(h[j]));
    }
    uint2 wh, wl;
    wh.x = (uint)h[0] | ((uint)h[1] << 16);  wh.y = (uint)h[2] | ((uint)h[3] << 16);
    wl.x = (uint)l[0] | ((uint)l[1] << 16);  wl.y = (uint)l[2] | ((uint)l[3] << 16);
    *(uint2*)&g_Ah[m * KTOT + k] = wh;
    *(uint2*)&g_Al[m * KTOT + k] = wl;
}

// ---------------- K2c: convert B = [kernel ; rec] -> TRANSPOSED hi/lo planes ----------------
// out[n][k] from in[k][n]; 32x32 tiles via SMEM.
__global__ void k_convert_Bt(const float* __restrict__ kernelW,
                             const float* __restrict__ recW) {
    __shared__ ushort sh[32][33];
    __shared__ ushort sl[32][33];
    const int t  = threadIdx.x;        // 256
    const int tx = t & 31;
    const int ty = t >> 5;             // 0..7
    const int n0 = blockIdx.x * 32;
    const int k0 = blockIdx.y * 32;

#pragma unroll
    for (int i = 0; i < 4; ++i) {
        const int kl = ty + i * 8;
        const int k  = k0 + kl;
        const int n  = n0 + tx;
        float v = (k < F) ? kernelW[k * FOURU + n] : recW[(k - F) * FOURU + n];
        ushort h = f2bf(v);
        sh[kl][tx] = h;
        sl[kl][tx] = f2bf(v - bf2f(h));
    }
    __syncthreads();

    const int row = t >> 3;            // n_local 0..31
    const int seg = t & 7;             // 4 k each
    ushort a = sh[seg * 4 + 0][row], b = sh[seg * 4 + 1][row];
    ushort c = sh[seg * 4 + 2][row], d = sh[seg * 4 + 3][row];
    uint2 w;
    w.x = (uint)a | ((uint)b << 16);  w.y = (uint)c | ((uint)d << 16);
    *(uint2*)&g_Bth[(n0 + row) * KTOT + k0 + seg * 4] = w;
    a = sl[seg * 4 + 0][row]; b = sl[seg * 4 + 1][row];
    c = sl[seg * 4 + 2][row]; d = sl[seg * 4 + 3][row];
    w.x = (uint)a | ((uint)b << 16);  w.y = (uint)c | ((uint)d << 16);
    *(uint2*)&g_Btl[(n0 + row) * KTOT + k0 + seg * 4] = w;
}

// ---------------- K3: tensor-core GEMM via mma.sync, 3-term bf16 split ----------------
// grid(64, 4): x = N-tile (32 cols), y = K-slice (256). Block 256 thr = 8 warps (4M x 2N).
// Warp tile: M32 x N16. zpart[by] += A_slice @ B_slice.
#define RSTRIDE 24   // padded SMEM row stride in ushorts (48 B) -> conflict-free frags

__global__ __launch_bounds__(256) void k_gemm_mma() {
    __shared__ ushort sAh[128 * RSTRIDE];
    __shared__ ushort sAl[128 * RSTRIDE];
    __shared__ ushort sBh[32 * RSTRIDE];
    __shared__ ushort sBl[32 * RSTRIDE];

    const int t    = threadIdx.x;
    const int wid  = t >> 5;
    const int lane = t & 31;
    const int g    = lane >> 2;
    const int tq   = lane & 3;
    const int warp_m = wid >> 1;      // 0..3
    const int warp_n = wid & 1;       // 0..1

    const int n_blk = blockIdx.x * 32;
    const int kbase = blockIdx.y * 256;
    float* __restrict__ Zout = g_zpart[blockIdx.y];

    // staging assignments
    const int rA = t >> 1;            // 0..127
    const int hA = t & 1;
    const ushort* pAh = g_Ah + rA * KTOT + kbase + hA * 8;
    const ushort* pAl = g_Al + rA * KTOT + kbase + hA * 8;
    const int  doB = (t < 128);
    const int  pB  = (t >> 6) & 1;    // 0=hi, 1=lo
    const int  rB  = (t & 63) >> 1;   // 0..31
    const int  hB  = t & 1;
    const ushort* pBg = (pB ? g_Btl : g_Bth) + (n_blk + rB) * KTOT + kbase + hB * 8;

    float acc[2][2][4];
#pragma unroll
    for (int i = 0; i < 2; ++i)
#pragma unroll
        for (int j = 0; j < 2; ++j)
#pragma unroll
            for (int q = 0; q < 4; ++q) acc[i][j][q] = 0.f;

    uint4 cAh = *(const uint4*)pAh;
    uint4 cAl = *(const uint4*)pAl;
    uint4 cB;
    if (doB) cB = *(const uint4*)pBg;

    for (int s = 0; s < 16; ++s) {
        *(uint4*)&sAh[rA * RSTRIDE + hA * 8] = cAh;
        *(uint4*)&sAl[rA * RSTRIDE + hA * 8] = cAl;
        if (doB) *(uint4*)&((pB ? sBl : sBh)[rB * RSTRIDE + hB * 8]) = cB;
        __syncthreads();

        if (s < 15) {
            cAh = *(const uint4*)(pAh + (s + 1) * 16);
            cAl = *(const uint4*)(pAl + (s + 1) * 16);
            if (doB) cB = *(const uint4*)(pBg + (s + 1) * 16);
        }

        // B fragments: 2 n-tiles x (hi, lo)
        uint bh[2][2], bl[2][2];
#pragma unroll
        for (int nt = 0; nt < 2; ++nt) {
            const int nrow = warp_n * 16 + nt * 8 + g;
            const uint* qh = (const uint*)&sBh[nrow * RSTRIDE];
            const uint* ql = (const uint*)&sBl[nrow * RSTRIDE];
            bh[nt][0] = qh[tq];  bh[nt][1] = qh[tq + 4];
            bl[nt][0] = ql[tq];  bl[nt][1] = ql[tq + 4];
        }

#pragma unroll
        for (int mt = 0; mt < 2; ++mt) {
            const int rb = warp_m * 32 + mt * 16;
            const uint* r0h = (const uint*)&sAh[(rb + g) * RSTRIDE];
            const uint* r1h = (const uint*)&sAh[(rb + g + 8) * RSTRIDE];
            const uint* r0l = (const uint*)&sAl[(rb + g) * RSTRIDE];
            const uint* r1l = (const uint*)&sAl[(rb + g + 8) * RSTRIDE];
            uint ah0 = r0h[tq], ah1 = r1h[tq], ah2 = r0h[tq + 4], ah3 = r1h[tq + 4];
            uint al0 = r0l[tq], al1 = r1l[tq], al2 = r0l[tq + 4], al3 = r1l[tq + 4];
#pragma unroll
            for (int nt = 0; nt < 2; ++nt) {
                mma16816(acc[mt][nt], ah0, ah1, ah2, ah3, bh[nt][0], bh[nt][1]);
                mma16816(acc[mt][nt], al0, al1, al2, al3, bh[nt][0], bh[nt][1]);
                mma16816(acc[mt][nt], ah0, ah1, ah2, ah3, bl[nt][0], bl[nt][1]);
            }
        }
        __syncthreads();
    }

#pragma unroll
    for (int mt = 0; mt < 2; ++mt)
#pragma unroll
        for (int nt = 0; nt < 2; ++nt) {
            const int m0 = warp_m * 32 + mt * 16 + g;
            const int nc = n_blk + warp_n * 16 + nt * 8 + 2 * tq;
            *(float2*)(Zout + m0 * FOURU + nc)       = make_float2(acc[mt][nt][0], acc[mt][nt][1]);
            *(float2*)(Zout + (m0 + 8) * FOURU + nc) = make_float2(acc[mt][nt][2], acc[mt][nt][3]);
        }
}

// ---------------- K4: gates + LSTM cell + scatter-max (float2) ----------------
__global__ void k_gates_scatter(const float* __restrict__ bias,
                                float* __restrict__ out_h,
                                float* __restrict__ out_newh,
                                float* __restrict__ out_newc) {
    const int i = blockIdx.x * 128 + threadIdx.x;  // 0 .. BS*U/2-1
    const int b = i >> 8;            // / (U/2)
    const int u = (i & 255) * 2;     // unit pair

    const int base = b * FOURU + u;
    float2 zi = make_float2(0.f, 0.f), zf = zi, zg = zi, zo = zi;
#pragma unroll
    for (int p = 0; p < 4; ++p) {
        const float* zp = g_zpart[p] + base;
        float2 a  = *(const float2*)(zp);
        float2 bb = *(const float2*)(zp + U);
        float2 c  = *(const float2*)(zp + 2 * U);
        float2 d  = *(const float2*)(zp + 3 * U);
        zi.x += a.x;  zi.y += a.y;
        zf.x += bb.x; zf.y += bb.y;
        zg.x += c.x;  zg.y += c.y;
        zo.x += d.x;  zo.y += d.y;
    }
    float2 bi = *(const float2*)(bias + u);
    float2 bf = *(const float2*)(bias + u + U);
    float2 bg = *(const float2*)(bias + u + 2 * U);
    float2 bo = *(const float2*)(bias + u + 3 * U);
    float2 c0 = *(const float2*)(g_c0 + b * U + u);

    float h0v, h1v, c0v, c1v;
    {
        float ig = fsig(zi.x + bi.x);
        float fg = fsig(zf.x + bf.x);
        float gg = ftanh_fast(zg.x + bg.x);
        float og = fsig(zo.x + bo.x);
        c0v = fg * c0.x + ig * gg;
        h0v = og * ftanh_fast(c0v);
    }
    {
        float ig = fsig(zi.y + bi.y);
        float fg = fsig(zf.y + bf.y);
        float gg = ftanh_fast(zg.y + bg.y);
        float og = fsig(zo.y + bo.y);
        c1v = fg * c0.y + ig * gg;
        h1v = og * ftanh_fast(c1v);
    }

    *(float2*)(out_h + b * U + u) = make_float2(h0v, h1v);

    const int cls = g_idx[b];
    float* nh = out_newh + cls * U + u;
    float* nc = out_newc + cls * U + u;
    atomicMaxFloat(nh,     h0v);
    atomicMaxFloat(nh + 1, h1v);
    atomicMaxFloat(nc,     c0v);
    atomicMaxFloat(nc + 1, c1v);
}

// ---------------- launch ----------------
extern "C" void kernel_launch(void* const* d_in, const int* in_sizes, int n_in,
                              void* d_out, int out_size) {
    const float* x        = (const float*)d_in[0];
    const float* logits   = (const float*)d_in[1];
    const float* h_states = (const float*)d_in[2];
    const float* c_states = (const float*)d_in[3];
    const float* kernelW  = (const float*)d_in[4];
    const float* recW     = (const float*)d_in[5];
    const float* bias     = (const float*)d_in[6];

    float* out      = (float*)d_out;
    float* out_h    = out;                    // (128, 512)
    float* out_newh = out + BS * U;           // (1024, 512)
    float* out_newc = out + BS * U + NC * U;  // (1024, 512)

    k_argmax_gather<<<BS, 256>>>(logits, h_states, c_states);
    k_convert_A<<<BS * KTOT / (256 * 4), 256>>>(x);                  // 128 blocks
    {
        dim3 gb(FOURU / 32, KTOT / 32);                              // (64, 32)
        k_convert_Bt<<<gb, 256>>>(kernelW, recW);
    }
    k_copy_states<<<(NC * U / 4 + 255) / 256, 256>>>(h_states, c_states, out_newh, out_newc);
    {
        dim3 gg(FOURU / 32, 4);                                      // (64, 4) = 256 blocks
        k_gemm_mma<<<gg, 256>>>();
    }
    k_gates_scatter<<<(BS * U / 2) / 128, 128>>>(bias, out_h, out_newh, out_newc);
}

// round 8
// speedup vs baseline: 1.0597x; 1.0597x over previous
#include <cuda_runtime.h>
#include <cstdint>

#define BS 128
#define NC 1024
#define U  512
#define F  512
#define FOURU 2048
#define KTOT 1024

typedef unsigned int  uint;
typedef unsigned short ushort;

// ---------------- scratch (no allocations allowed) ----------------
__device__ float  g_h0[BS * U];
__device__ float  g_c0[BS * U];
__device__ int    g_idx[BS];
__device__ float  g_zpart[2][BS * FOURU];         // z = sum of 2 K-slices + bias
__device__ ushort g_Ah[BS * KTOT];                // A=[x|h0] hi plane, [m][k]
__device__ ushort g_Al[BS * KTOT];                // lo plane

// ---------------- helpers ----------------
__device__ __forceinline__ ushort f2bf(float a) {
    ushort u;
    asm("cvt.rn.bf16.f32 %0, %1;" : "=h"(u) : "f"(a));
    return u;
}
__device__ __forceinline__ float bf2f(ushort u) {
    float f;
    asm("cvt.f32.bf16 %0, %1;" : "=f"(f) : "h"(u));
    return f;
}
__device__ __forceinline__ void atomicMaxFloat(float* addr, float val) {
    int* ia = (int*)addr;
    int old = *ia;
    while (__int_as_float(old) < val) {
        int assumed = old;
        old = atomicCAS(ia, assumed, __float_as_int(val));
        if (old == assumed) break;
    }
}
__device__ __forceinline__ float fsig(float x) {
    float e, r;
    asm("ex2.approx.ftz.f32 %0, %1;" : "=f"(e) : "f"(-x * 1.4426950408889634f));
    asm("rcp.approx.ftz.f32 %0, %1;" : "=f"(r) : "f"(1.0f + e));
    return r;
}
__device__ __forceinline__ float ftanh_fast(float x) {
    return 2.0f * fsig(2.0f * x) - 1.0f;
}
__device__ __forceinline__ void mma16816(float* d, uint a0, uint a1, uint a2, uint a3,
                                         uint b0, uint b1) {
    asm volatile(
        "mma.sync.aligned.m16n8k16.row.col.f32.bf16.bf16.f32 "
        "{%0,%1,%2,%3}, {%4,%5,%6,%7}, {%8,%9}, {%0,%1,%2,%3};"
        : "+f"(d[0]), "+f"(d[1]), "+f"(d[2]), "+f"(d[3])
        : "r"(a0), "r"(a1), "r"(a2), "r"(a3), "r"(b0), "r"(b1));
}

// ---------------- K1: per-row argmax of logits + gather states ----------------
__global__ void k_argmax_gather(const float* __restrict__ logits,
                                const float* __restrict__ h_states,
                                const float* __restrict__ c_states) {
    const int b = blockIdx.x;
    const int t = threadIdx.x;                 // 256 threads
    const float* row = logits + b * NC;

    float best = -3.4e38f;
    int   bi   = 0x7fffffff;
#pragma unroll
    for (int j = 0; j < NC; j += 256) {
        float v = row[j + t];
        int   i = j + t;
        if (v > best || (v == best && i < bi)) { best = v; bi = i; }
    }
#pragma unroll
    for (int off = 16; off; off >>= 1) {
        float ov = __shfl_down_sync(0xffffffffu, best, off);
        int   oi = __shfl_down_sync(0xffffffffu, bi,   off);
        if (ov > best || (ov == best && oi < bi)) { best = ov; bi = oi; }
    }
    __shared__ float sv[8];
    __shared__ int   si[8];
    __shared__ int   s_idx;
    if ((t & 31) == 0) { sv[t >> 5] = best; si[t >> 5] = bi; }
    __syncthreads();
    if (t == 0) {
        best = sv[0]; bi = si[0];
#pragma unroll
        for (int w = 1; w < 8; ++w)
            if (sv[w] > best || (sv[w] == best && si[w] < bi)) { best = sv[w]; bi = si[w]; }
        s_idx = bi;
        g_idx[b] = bi;
    }
    __syncthreads();
    const int idx = s_idx;

    const float4* hs = (const float4*)(h_states + idx * U);
    const float4* cs = (const float4*)(c_states + idx * U);
    float4* hd = (float4*)(g_h0 + b * U);
    float4* cd = (float4*)(g_c0 + b * U);
    if (t < U / 4) { hd[t] = hs[t]; cd[t] = cs[t]; }
}

// ---------------- K2: copy states into output (base for scatter-max) ----------------
// 2 float4s per array per thread for MLP=4.
__global__ void k_copy_states(const float* __restrict__ h_states,
                              const float* __restrict__ c_states,
                              float* __restrict__ out_newh,
                              float* __restrict__ out_newc) {
    const int i = blockIdx.x * 256 + threadIdx.x;   // 0..65535
    const int HALF = NC * U / 8;                    // 65536 float4s per half
    float4 h1 = ((const float4*)h_states)[i];
    float4 h2 = ((const float4*)h_states)[i + HALF];
    float4 c1 = ((const float4*)c_states)[i];
    float4 c2 = ((const float4*)c_states)[i + HALF];
    ((float4*)out_newh)[i]        = h1;
    ((float4*)out_newh)[i + HALF] = h2;
    ((float4*)out_newc)[i]        = c1;
    ((float4*)out_newc)[i + HALF] = c2;
}

// ---------------- K2b: convert A = [x | h0] into hi/lo bf16 planes ----------------
__global__ void k_convert_A(const float* __restrict__ x) {
    const int i4 = (blockIdx.x * 256 + threadIdx.x) * 4;   // 128 blocks x 256
    const int m = i4 >> 10;
    const int k = i4 & (KTOT - 1);
    float4 v;
    if (k < F) v = *(const float4*)(x + m * F + k);
    else       v = *(const float4*)(g_h0 + m * U + (k - F));

    ushort h[4], l[4];
    float* vp = (float*)&v;
#pragma unroll
    for (int j = 0; j < 4; ++j) {
        h[j] = f2bf(vp[j]);
        l[j] = f2bf(vp[j] - bf2f(h[j]));
    }
    uint2 wh, wl;
    wh.x = (uint)h[0] | ((uint)h[1] << 16);  wh.y = (uint)h[2] | ((uint)h[3] << 16);
    wl.x = (uint)l[0] | ((uint)l[1] << 16);  wl.y = (uint)l[2] | ((uint)l[3] << 16);
    *(uint2*)&g_Ah[m * KTOT + k] = wh;
    *(uint2*)&g_Al[m * KTOT + k] = wl;
}

// ---------------- K3: tensor-core GEMM, 3-term bf16 split, in-kernel B convert ----
// grid(64, 2): x = N-tile (32 cols), y = K-slice (512 = kernel | rec).
// Block 256 thr = 8 warps (4M x 2N), warp tile M32 x N16, 32 iters of k16.
#define RSTRIDE 24   // A row stride in ushorts (48 B): frag reads conflict-free
#define BSTRU 12     // B row stride in uints (48 B): reads & remapped stores conflict-free

__global__ __launch_bounds__(256) void k_gemm_mma(const float* __restrict__ kernelW,
                                                  const float* __restrict__ recW) {
    __shared__ ushort sAh[2][128 * RSTRIDE];
    __shared__ ushort sAl[2][128 * RSTRIDE];
    __shared__ uint   sBh[2][32 * BSTRU];
    __shared__ uint   sBl[2][32 * BSTRU];

    const int t    = threadIdx.x;
    const int wid  = t >> 5;
    const int lane = t & 31;
    const int g    = lane >> 2;
    const int tq   = lane & 3;
    const int warp_m = wid >> 1;      // 0..3
    const int warp_n = wid & 1;       // 0..1

    const int n_blk  = blockIdx.x * 32;
    const int kslice = blockIdx.y;
    const int kbase  = kslice * 512;
    float* __restrict__ Zout = g_zpart[kslice];
    const float* __restrict__ Bsl = kslice ? recW : kernelW;   // [512][2048]

    // A staging: rA = row, hA selects 8-ushort half of the k16 chunk
    const int rA = t >> 1;            // 0..127
    const int hA = t & 1;
    const ushort* pAh = g_Ah + rA * KTOT + kbase + hA * 8;
    const ushort* pAl = g_Al + rA * KTOT + kbase + hA * 8;

    // B staging: warp lanes span 4 n-rows x 8 k-pairs -> conflict-free STS.32,
    // gmem rows coalesced across the 8 warps (consecutive nl in same line).
    const int nl  = t >> 3;           // 0..31
    const int klp = t & 7;            // 0..7 (k-pair)
    const float* pB = Bsl + (2 * klp) * FOURU + n_blk + nl;

    float acc[2][2][4];
#pragma unroll
    for (int i = 0; i < 2; ++i)
#pragma unroll
        for (int j = 0; j < 2; ++j)
#pragma unroll
            for (int q = 0; q < 4; ++q) acc[i][j][q] = 0.f;

    uint4 cAh = *(const uint4*)pAh;
    uint4 cAl = *(const uint4*)pAl;
    float b0 = pB[0];
    float b1 = pB[FOURU];

    for (int s = 0; s < 32; ++s) {
        const int buf = s & 1;
        *(uint4*)&sAh[buf][rA * RSTRIDE + hA * 8] = cAh;
        *(uint4*)&sAl[buf][rA * RSTRIDE + hA * 8] = cAl;
        {
            ushort h0 = f2bf(b0), h1 = f2bf(b1);
            ushort l0 = f2bf(b0 - bf2f(h0)), l1 = f2bf(b1 - bf2f(h1));
            sBh[buf][nl * BSTRU + klp] = (uint)h0 | ((uint)h1 << 16);
            sBl[buf][nl * BSTRU + klp] = (uint)l0 | ((uint)l1 << 16);
        }
        __syncthreads();

        if (s < 31) {
            cAh = *(const uint4*)(pAh + (s + 1) * 16);
            cAl = *(const uint4*)(pAl + (s + 1) * 16);
            const float* nB = pB + (s + 1) * 16 * FOURU;
            b0 = nB[0];
            b1 = nB[FOURU];
        }

        // B fragments: 2 n-tiles x (hi, lo)
        uint bh[2][2], bl[2][2];
#pragma unroll
        for (int nt = 0; nt < 2; ++nt) {
            const int nrow = warp_n * 16 + nt * 8 + g;
            const uint* qh = &sBh[buf][nrow * BSTRU];
            const uint* ql = &sBl[buf][nrow * BSTRU];
            bh[nt][0] = qh[tq];  bh[nt][1] = qh[tq + 4];
            bl[nt][0] = ql[tq];  bl[nt][1] = ql[tq + 4];
        }

#pragma unroll
        for (int mt = 0; mt < 2; ++mt) {
            const int rb = warp_m * 32 + mt * 16;
            const uint* r0h = (const uint*)&sAh[buf][(rb + g) * RSTRIDE];
            const uint* r1h = (const uint*)&sAh[buf][(rb + g + 8) * RSTRIDE];
            const uint* r0l = (const uint*)&sAl[buf][(rb + g) * RSTRIDE];
            const uint* r1l = (const uint*)&sAl[buf][(rb + g + 8) * RSTRIDE];
            uint ah0 = r0h[tq], ah1 = r1h[tq], ah2 = r0h[tq + 4], ah3 = r1h[tq + 4];
            uint al0 = r0l[tq], al1 = r1l[tq], al2 = r0l[tq + 4], al3 = r1l[tq + 4];
#pragma unroll
            for (int nt = 0; nt < 2; ++nt) {
                mma16816(acc[mt][nt], ah0, ah1, ah2, ah3, bh[nt][0], bh[nt][1]);
                mma16816(acc[mt][nt], al0, al1, al2, al3, bh[nt][0], bh[nt][1]);
                mma16816(acc[mt][nt], ah0, ah1, ah2, ah3, bl[nt][0], bl[nt][1]);
            }
        }
        __syncthreads();
    }

#pragma unroll
    for (int mt = 0; mt < 2; ++mt)
#pragma unroll
        for (int nt = 0; nt < 2; ++nt) {
            const int m0 = warp_m * 32 + mt * 16 + g;
            const int nc = n_blk + warp_n * 16 + nt * 8 + 2 * tq;
            *(float2*)(Zout + m0 * FOURU + nc)       = make_float2(acc[mt][nt][0], acc[mt][nt][1]);
            *(float2*)(Zout + (m0 + 8) * FOURU + nc) = make_float2(acc[mt][nt][2], acc[mt][nt][3]);
        }
}

// ---------------- K4: gates + LSTM cell + scatter-max (float2) ----------------
__global__ void k_gates_scatter(const float* __restrict__ bias,
                                float* __restrict__ out_h,
                                float* __restrict__ out_newh,
                                float* __restrict__ out_newc) {
    const int i = blockIdx.x * 128 + threadIdx.x;  // 0 .. BS*U/2-1
    const int b = i >> 8;            // / (U/2)
    const int u = (i & 255) * 2;     // unit pair

    const int base = b * FOURU + u;
    float2 zi = make_float2(0.f, 0.f), zf = zi, zg = zi, zo = zi;
#pragma unroll
    for (int p = 0; p < 2; ++p) {
        const float* zp = g_zpart[p] + base;
        float2 a  = *(const float2*)(zp);
        float2 bb = *(const float2*)(zp + U);
        float2 c  = *(const float2*)(zp + 2 * U);
        float2 d  = *(const float2*)(zp + 3 * U);
        zi.x += a.x;  zi.y += a.y;
        zf.x += bb.x; zf.y += bb.y;
        zg.x += c.x;  zg.y += c.y;
        zo.x += d.x;  zo.y += d.y;
    }
    float2 bi = *(const float2*)(bias + u);
    float2 bf = *(const float2*)(bias + u + U);
    float2 bg = *(const float2*)(bias + u + 2 * U);
    float2 bo = *(const float2*)(bias + u + 3 * U);
    float2 c0 = *(const float2*)(g_c0 + b * U + u);

    float h0v, h1v, c0v, c1v;
    {
        float ig = fsig(zi.x + bi.x);
        float fg = fsig(zf.x + bf.x);
        float gg = ftanh_fast(zg.x + bg.x);
        float og = fsig(zo.x + bo.x);
        c0v = fg * c0.x + ig * gg;
        h0v = og * ftanh_fast(c0v);
    }
    {
        float ig = fsig(zi.y + bi.y);
        float fg = fsig(zf.y + bf.y);
        float gg = ftanh_fast(zg.y + bg.y);
        float og = fsig(zo.y + bo.y);
        c1v = fg * c0.y + ig * gg;
        h1v = og * ftanh_fast(c1v);
    }

    *(float2*)(out_h + b * U + u) = make_float2(h0v, h1v);

    const int cls = g_idx[b];
    float* nh = out_newh + cls * U + u;
    float* nc = out_newc + cls * U + u;
    atomicMaxFloat(nh,     h0v);
    atomicMaxFloat(nh + 1, h1v);
    atomicMaxFloat(nc,     c0v);
    atomicMaxFloat(nc + 1, c1v);
}

// ---------------- launch ----------------
extern "C" void kernel_launch(void* const* d_in, const int* in_sizes, int n_in,
                              void* d_out, int out_size) {
    const float* x        = (const float*)d_in[0];
    const float* logits   = (const float*)d_in[1];
    const float* h_states = (const float*)d_in[2];
    const float* c_states = (const float*)d_in[3];
    const float* kernelW  = (const float*)d_in[4];
    const float* recW     = (const float*)d_in[5];
    const float* bias     = (const float*)d_in[6];

    float* out      = (float*)d_out;
    float* out_h    = out;                    // (128, 512)
    float* out_newh = out + BS * U;           // (1024, 512)
    float* out_newc = out + BS * U + NC * U;  // (1024, 512)

    k_argmax_gather<<<BS, 256>>>(logits, h_states, c_states);
    k_convert_A<<<128, 256>>>(x);
    k_copy_states<<<256, 256>>>(h_states, c_states, out_newh, out_newc);
    {
        dim3 gg(FOURU / 32, 2);               // (64, 2) = 128 blocks
        k_gemm_mma<<<gg, 256>>>(kernelW, recW);
    }
    k_gates_scatter<<<(BS * U / 2) / 128, 128>>>(bias, out_h, out_newh, out_newc);
}

// round 9
// speedup vs baseline: 1.1996x; 1.1320x over previous
#include <cuda_runtime.h>
#include <cstdint>

#define BS 128
#define NC 1024
#define U  512
#define F  512
#define FOURU 2048
#define KTOT 1024

typedef unsigned int  uint;
typedef unsigned short ushort;

// ---------------- scratch (no allocations allowed) ----------------
__device__ float  g_h0[BS * U];
__device__ float  g_c0[BS * U];
__device__ int    g_idx[BS];
__device__ float  g_zpart[4][BS * FOURU];         // z = sum of 4 K-slices + bias
__device__ ushort g_Ah[BS * KTOT];                // A=[x|h0] hi plane, [m][k]
__device__ ushort g_Al[BS * KTOT];                // lo plane

// ---------------- helpers ----------------
__device__ __forceinline__ ushort f2bf(float a) {
    ushort u;
    asm("cvt.rn.bf16.f32 %0, %1;" : "=h"(u) : "f"(a));
    return u;
}
__device__ __forceinline__ float bf2f(ushort u) {
    float f;
    asm("cvt.f32.bf16 %0, %1;" : "=f"(f) : "h"(u));
    return f;
}
__device__ __forceinline__ void atomicMaxFloat(float* addr, float val) {
    int* ia = (int*)addr;
    int old = *ia;
    while (__int_as_float(old) < val) {
        int assumed = old;
        old = atomicCAS(ia, assumed, __float_as_int(val));
        if (old == assumed) break;
    }
}
__device__ __forceinline__ float fsig(float x) {
    float e, r;
    asm("ex2.approx.ftz.f32 %0, %1;" : "=f"(e) : "f"(-x * 1.4426950408889634f));
    asm("rcp.approx.ftz.f32 %0, %1;" : "=f"(r) : "f"(1.0f + e));
    return r;
}
__device__ __forceinline__ float ftanh_fast(float x) {
    return 2.0f * fsig(2.0f * x) - 1.0f;
}
__device__ __forceinline__ void mma16816(float* d, uint a0, uint a1, uint a2, uint a3,
                                         uint b0, uint b1) {
    asm volatile(
        "mma.sync.aligned.m16n8k16.row.col.f32.bf16.bf16.f32 "
        "{%0,%1,%2,%3}, {%4,%5,%6,%7}, {%8,%9}, {%0,%1,%2,%3};"
        : "+f"(d[0]), "+f"(d[1]), "+f"(d[2]), "+f"(d[3])
        : "r"(a0), "r"(a1), "r"(a2), "r"(a3), "r"(b0), "r"(b1));
}

// ---------------- K1: per-row argmax of logits + gather states ----------------
__global__ void k_argmax_gather(const float* __restrict__ logits,
                                const float* __restrict__ h_states,
                                const float* __restrict__ c_states) {
    const int b = blockIdx.x;
    const int t = threadIdx.x;                 // 256 threads
    const float* row = logits + b * NC;

    float best = -3.4e38f;
    int   bi   = 0x7fffffff;
#pragma unroll
    for (int j = 0; j < NC; j += 256) {
        float v = row[j + t];
        int   i = j + t;
        if (v > best || (v == best && i < bi)) { best = v; bi = i; }
    }
#pragma unroll
    for (int off = 16; off; off >>= 1) {
        float ov = __shfl_down_sync(0xffffffffu, best, off);
        int   oi = __shfl_down_sync(0xffffffffu, bi,   off);
        if (ov > best || (ov == best && oi < bi)) { best = ov; bi = oi; }
    }
    __shared__ float sv[8];
    __shared__ int   si[8];
    __shared__ int   s_idx;
    if ((t & 31) == 0) { sv[t >> 5] = best; si[t >> 5] = bi; }
    __syncthreads();
    if (t == 0) {
        best = sv[0]; bi = si[0];
#pragma unroll
        for (int w = 1; w < 8; ++w)
            if (sv[w] > best || (sv[w] == best && si[w] < bi)) { best = sv[w]; bi = si[w]; }
        s_idx = bi;
        g_idx[b] = bi;
    }
    __syncthreads();
    const int idx = s_idx;

    const float4* hs = (const float4*)(h_states + idx * U);
    const float4* cs = (const float4*)(c_states + idx * U);
    float4* hd = (float4*)(g_h0 + b * U);
    float4* cd = (float4*)(g_c0 + b * U);
    if (t < U / 4) { hd[t] = hs[t]; cd[t] = cs[t]; }
}

// ---------------- K2: copy states into output (base for scatter-max) ----------------
__global__ void k_copy_states(const float* __restrict__ h_states,
                              const float* __restrict__ c_states,
                              float* __restrict__ out_newh,
                              float* __restrict__ out_newc) {
    const int i = blockIdx.x * 256 + threadIdx.x;   // 0..65535
    const int HALF = NC * U / 8;                    // 65536 float4s per half
    float4 h1 = ((const float4*)h_states)[i];
    float4 h2 = ((const float4*)h_states)[i + HALF];
    float4 c1 = ((const float4*)c_states)[i];
    float4 c2 = ((const float4*)c_states)[i + HALF];
    ((float4*)out_newh)[i]        = h1;
    ((float4*)out_newh)[i + HALF] = h2;
    ((float4*)out_newc)[i]        = c1;
    ((float4*)out_newc)[i + HALF] = c2;
}

// ---------------- K2b: convert A = [x | h0] into hi/lo bf16 planes ----------------
__global__ void k_convert_A(const float* __restrict__ x) {
    const int i4 = (blockIdx.x * 256 + threadIdx.x) * 4;   // 128 blocks x 256
    const int m = i4 >> 10;
    const int k = i4 & (KTOT - 1);
    float4 v;
    if (k < F) v = *(const float4*)(x + m * F + k);
    else       v = *(const float4*)(g_h0 + m * U + (k - F));

    ushort h[4], l[4];
    float* vp = (float*)&v;
#pragma unroll
    for (int j = 0; j < 4; ++j) {
        h[j] = f2bf(vp[j]);
        l[j] = f2bf(vp[j] - bf2f(h[j]));
    }
    uint2 wh, wl;
    wh.x = (uint)h[0] | ((uint)h[1] << 16);  wh.y = (uint)h[2] | ((uint)h[3] << 16);
    wl.x = (uint)l[0] | ((uint)l[1] << 16);  wl.y = (uint)l[2] | ((uint)l[3] << 16);
    *(uint2*)&g_Ah[m * KTOT + k] = wh;
    *(uint2*)&g_Al[m * KTOT + k] = wl;
}

// ---------------- K3: tensor-core GEMM, 3-term bf16 split, in-kernel B convert ----
// grid(64, 4): x = N-tile (32 cols), y = K-slice (256 rows of combined K).
// Block 256 thr = 8 warps (4M x 2N), warp tile M32 x N16, 16 iters of k16.
#define RSTRIDE 24   // A row stride in ushorts (48 B): frag reads conflict-free
#define BSTRU 12     // B row stride in uints (48 B): frag reads conflict-free

__global__ __launch_bounds__(256) void k_gemm_mma(const float* __restrict__ kernelW,
                                                  const float* __restrict__ recW) {
    __shared__ ushort sAh[2][128 * RSTRIDE];
    __shared__ ushort sAl[2][128 * RSTRIDE];
    __shared__ uint   sBh[2][32 * BSTRU];
    __shared__ uint   sBl[2][32 * BSTRU];

    const int t    = threadIdx.x;
    const int wid  = t >> 5;
    const int lane = t & 31;
    const int g    = lane >> 2;
    const int tq   = lane & 3;
    const int warp_m = wid >> 1;      // 0..3
    const int warp_n = wid & 1;       // 0..1

    const int n_blk  = blockIdx.x * 32;
    const int kslice = blockIdx.y;                 // 0..3
    const int kbase  = kslice * 256;               // offset in combined K
    float* __restrict__ Zout = g_zpart[kslice];
    const float* __restrict__ Bsl = (kslice < 2) ? kernelW : recW;  // [512][2048]
    const int koff = (kslice & 1) * 256;           // row offset within that weight

    // A staging: rA = row, hA selects 8-ushort half of the k16 chunk
    const int rA = t >> 1;            // 0..127
    const int hA = t & 1;
    const ushort* pAh = g_Ah + rA * KTOT + kbase + hA * 8;
    const ushort* pAl = g_Al + rA * KTOT + kbase + hA * 8;

    // B staging: lane-major in n => fully coalesced gmem (warp = 32 consecutive n,
    // one k-pair per warp). SMEM store is 4-way bank-conflicted but rare (2/iter);
    // fragment reads stay conflict-free.
    const int nl  = t & 31;           // 0..31 (lane)
    const int klp = t >> 5;           // 0..7 (k-pair = warp)
    const float* pB = Bsl + (koff + 2 * klp) * FOURU + n_blk + nl;

    float acc[2][2][4];
#pragma unroll
    for (int i = 0; i < 2; ++i)
#pragma unroll
        for (int j = 0; j < 2; ++j)
#pragma unroll
            for (int q = 0; q < 4; ++q) acc[i][j][q] = 0.f;

    uint4 cAh = *(const uint4*)pAh;
    uint4 cAl = *(const uint4*)pAl;
    float b0 = pB[0];
    float b1 = pB[FOURU];

    for (int s = 0; s < 16; ++s) {
        const int buf = s & 1;
        *(uint4*)&sAh[buf][rA * RSTRIDE + hA * 8] = cAh;
        *(uint4*)&sAl[buf][rA * RSTRIDE + hA * 8] = cAl;
        {
            ushort h0 = f2bf(b0), h1 = f2bf(b1);
            ushort l0 = f2bf(b0 - bf2f(h0)), l1 = f2bf(b1 - bf2f(h1));
            sBh[buf][nl * BSTRU + klp] = (uint)h0 | ((uint)h1 << 16);
            sBl[buf][nl * BSTRU + klp] = (uint)l0 | ((uint)l1 << 16);
        }
        __syncthreads();

        if (s < 15) {
            cAh = *(const uint4*)(pAh + (s + 1) * 16);
            cAl = *(const uint4*)(pAl + (s + 1) * 16);
            const float* nB = pB + (s + 1) * 16 * FOURU;
            b0 = nB[0];
            b1 = nB[FOURU];
        }

        // B fragments: 2 n-tiles x (hi, lo)
        uint bh[2][2], bl[2][2];
#pragma unroll
        for (int nt = 0; nt < 2; ++nt) {
            const int nrow = warp_n * 16 + nt * 8 + g;
            const uint* qh = &sBh[buf][nrow * BSTRU];
            const uint* ql = &sBl[buf][nrow * BSTRU];
            bh[nt][0] = qh[tq];  bh[nt][1] = qh[tq + 4];
            bl[nt][0] = ql[tq];  bl[nt][1] = ql[tq + 4];
        }

#pragma unroll
        for (int mt = 0; mt < 2; ++mt) {
            const int rb = warp_m * 32 + mt * 16;
            const uint* r0h = (const uint*)&sAh[buf][(rb + g) * RSTRIDE];
            const uint* r1h = (const uint*)&sAh[buf][(rb + g + 8) * RSTRIDE];
            const uint* r0l = (const uint*)&sAl[buf][(rb + g) * RSTRIDE];
            const uint* r1l = (const uint*)&sAl[buf][(rb + g + 8) * RSTRIDE];
            uint ah0 = r0h[tq], ah1 = r1h[tq], ah2 = r0h[tq + 4], ah3 = r1h[tq + 4];
            uint al0 = r0l[tq], al1 = r1l[tq], al2 = r0l[tq + 4], al3 = r1l[tq + 4];
#pragma unroll
            for (int nt = 0; nt < 2; ++nt) {
                mma16816(acc[mt][nt], ah0, ah1, ah2, ah3, bh[nt][0], bh[nt][1]);
                mma16816(acc[mt][nt], al0, al1, al2, al3, bh[nt][0], bh[nt][1]);
                mma16816(acc[mt][nt], ah0, ah1, ah2, ah3, bl[nt][0], bl[nt][1]);
            }
        }
        __syncthreads();
    }

#pragma unroll
    for (int mt = 0; mt < 2; ++mt)
#pragma unroll
        for (int nt = 0; nt < 2; ++nt) {
            const int m0 = warp_m * 32 + mt * 16 + g;
            const int nc = n_blk + warp_n * 16 + nt * 8 + 2 * tq;
            *(float2*)(Zout + m0 * FOURU + nc)       = make_float2(acc[mt][nt][0], acc[mt][nt][1]);
            *(float2*)(Zout + (m0 + 8) * FOURU + nc) = make_float2(acc[mt][nt][2], acc[mt][nt][3]);
        }
}

// ---------------- K4: gates + LSTM cell + scatter-max (float2) ----------------
__global__ void k_gates_scatter(const float* __restrict__ bias,
                                float* __restrict__ out_h,
                                float* __restrict__ out_newh,
                                float* __restrict__ out_newc) {
    const int i = blockIdx.x * 128 + threadIdx.x;  // 0 .. BS*U/2-1
    const int b = i >> 8;            // / (U/2)
    const int u = (i & 255) * 2;     // unit pair

    const int base = b * FOURU + u;
    float2 zi = make_float2(0.f, 0.f), zf = zi, zg = zi, zo = zi;
#pragma unroll
    for (int p = 0; p < 4; ++p) {
        const float* zp = g_zpart[p] + base;
        float2 a  = *(const float2*)(zp);
        float2 bb = *(const float2*)(zp + U);
        float2 c  = *(const float2*)(zp + 2 * U);
        float2 d  = *(const float2*)(zp + 3 * U);
        zi.x += a.x;  zi.y += a.y;
        zf.x += bb.x; zf.y += bb.y;
        zg.x += c.x;  zg.y += c.y;
        zo.x += d.x;  zo.y += d.y;
    }
    float2 bi = *(const float2*)(bias + u);
    float2 bf = *(const float2*)(bias + u + U);
    float2 bg = *(const float2*)(bias + u + 2 * U);
    float2 bo = *(const float2*)(bias + u + 3 * U);
    float2 c0 = *(const float2*)(g_c0 + b * U + u);

    float h0v, h1v, c0v, c1v;
    {
        float ig = fsig(zi.x + bi.x);
        float fg = fsig(zf.x + bf.x);
        float gg = ftanh_fast(zg.x + bg.x);
        float og = fsig(zo.x + bo.x);
        c0v = fg * c0.x + ig * gg;
        h0v = og * ftanh_fast(c0v);
    }
    {
        float ig = fsig(zi.y + bi.y);
        float fg = fsig(zf.y + bf.y);
        float gg = ftanh_fast(zg.y + bg.y);
        float og = fsig(zo.y + bo.y);
        c1v = fg * c0.y + ig * gg;
        h1v = og * ftanh_fast(c1v);
    }

    *(float2*)(out_h + b * U + u) = make_float2(h0v, h1v);

    const int cls = g_idx[b];
    float* nh = out_newh + cls * U + u;
    float* nc = out_newc + cls * U + u;
    atomicMaxFloat(nh,     h0v);
    atomicMaxFloat(nh + 1, h1v);
    atomicMaxFloat(nc,     c0v);
    atomicMaxFloat(nc + 1, c1v);
}

// ---------------- launch ----------------
extern "C" void kernel_launch(void* const* d_in, const int* in_sizes, int n_in,
                              void* d_out, int out_size) {
    const float* x        = (const float*)d_in[0];
    const float* logits   = (const float*)d_in[1];
    const float* h_states = (const float*)d_in[2];
    const float* c_states = (const float*)d_in[3];
    const float* kernelW  = (const float*)d_in[4];
    const float* recW     = (const float*)d_in[5];
    const float* bias     = (const float*)d_in[6];

    float* out      = (float*)d_out;
    float* out_h    = out;                    // (128, 512)
    float* out_newh = out + BS * U;           // (1024, 512)
    float* out_newc = out + BS * U + NC * U;  // (1024, 512)

    k_argmax_gather<<<BS, 256>>>(logits, h_states, c_states);
    k_convert_A<<<128, 256>>>(x);
    k_copy_states<<<256, 256>>>(h_states, c_states, out_newh, out_newc);
    {
        dim3 gg(FOURU / 32, 4);               // (64, 4) = 256 blocks
        k_gemm_mma<<<gg, 256>>>(kernelW, recW);
    }
    k_gates_scatter<<<(BS * U / 2) / 128, 128>>>(bias, out_h, out_newh, out_newc);
}